// round 1
// baseline (speedup 1.0000x reference)
#include <cuda_runtime.h>

// Problem constants
#define BATCH 8
#define NPX   (512*512)          // 262144 pixels per sample
#define BPS   32                 // K1 blocks per sample
#define CH3   16                 // chunks per (array,sample) in K3/K5
#define NBIN  4096
#define EPS2  1e-12f
#define SCALE_D 1099511627776.0  // 2^40 fixed-point scale

// ---------------- device scratch (static; no allocations) ----------------
__device__ float    g_valA[BATCH*NPX];          // alpha-diff values
__device__ float    g_valC[BATCH*NPX];          // comp-diff values
__device__ unsigned g_count[BATCH];             // # unknown pixels
__device__ int      g_k[BATCH];                 // top-k count per sample
__device__ unsigned g_hist1[2][BATCH][NBIN];    // top-12-bit histogram
__device__ unsigned g_hist2[2][BATCH][NBIN];    // next-12-bit histogram
__device__ unsigned g_hist3[2][BATCH][256];     // low-8-bit histogram
__device__ unsigned g_pfx12[2][BATCH];
__device__ unsigned g_pfx24[2][BATCH];
__device__ unsigned g_krem1[2][BATCH];
__device__ unsigned g_krem2[2][BATCH];
__device__ unsigned long long g_sumAbove[2][BATCH];

// ---------------- K0: zero the accumulators ----------------
__global__ void k_zero() {
    unsigned idx = blockIdx.x * blockDim.x + threadIdx.x;
    unsigned H = 2u * BATCH * NBIN;                 // 65536
    if (idx < H) {
        ((unsigned*)g_hist1)[idx] = 0u;
        ((unsigned*)g_hist2)[idx] = 0u;
    }
    if (idx < 2u * BATCH * 256u) ((unsigned*)g_hist3)[idx] = 0u;
    if (idx < BATCH)             g_count[idx] = 0u;
    if (idx < 2u * BATCH)        ((unsigned long long*)g_sumAbove)[idx] = 0ull;
}

// ---------------- K1: fused value compute + count + 12-bit histogram ----------------
__global__ __launch_bounds__(256) void k_compute(
    const float* __restrict__ image, const float* __restrict__ alpha,
    const float* __restrict__ pred,  const int*   __restrict__ trimap,
    const float* __restrict__ fg,    const float* __restrict__ bg)
{
    __shared__ unsigned shA[NBIN];
    __shared__ unsigned shC[NBIN];
    __shared__ unsigned shCnt;
    for (int i = threadIdx.x; i < NBIN; i += 256) { shA[i] = 0u; shC[i] = 0u; }
    if (threadIdx.x == 0) shCnt = 0u;
    __syncthreads();

    const int b     = blockIdx.x / BPS;
    const int chunk = blockIdx.x % BPS;
    const int base  = chunk * (NPX / BPS);          // pixel offset within sample
    const int CH4   = NPX / 4;                      // channel stride in float4

    const float4* al4 = (const float4*)(alpha  + (size_t)b * NPX + base);
    const float4* pr4 = (const float4*)(pred   + (size_t)b * NPX + base);
    const int4*   tm4 = (const int4*)  (trimap + (size_t)b * NPX + base);
    const float4* im4 = (const float4*)(image  + (size_t)b * 3 * NPX + base);
    const float4* fg4 = (const float4*)(fg     + (size_t)b * 3 * NPX + base);
    const float4* bg4 = (const float4*)(bg     + (size_t)b * 3 * NPX + base);
    float4* oA = (float4*)(g_valA + (size_t)b * NPX + base);
    float4* oC = (float4*)(g_valC + (size_t)b * NPX + base);

    unsigned cnt = 0;
    const int NIT = (NPX / BPS) / 4;                // 2048 float4 groups per block
    for (int i = threadIdx.x; i < NIT; i += 256) {
        int4   t  = tm4[i];
        float4 a  = al4[i], p = pr4[i];
        float4 i0 = im4[i], i1 = im4[i + CH4], i2 = im4[i + 2*CH4];
        float4 f0 = fg4[i], f1 = fg4[i + CH4], f2 = fg4[i + 2*CH4];
        float4 g0 = bg4[i], g1 = bg4[i + CH4], g2 = bg4[i + 2*CH4];
        float4 va, vc;
        #pragma unroll
        for (int j = 0; j < 4; j++) {
            int   tt = ((const int*)&t)[j];
            float pp = ((const float*)&p)[j];
            float da, dc;
            if (tt == 128) {
                float d  = __fdiv_rn(((const float*)&a)[j], 255.0f) - pp;
                da = __fsqrt_rn(fmaf(d, d, EPS2));
                float q  = 1.0f - pp;
                float d0 = ((const float*)&i0)[j] - (((const float*)&f0)[j]*pp + q*((const float*)&g0)[j]);
                float d1 = ((const float*)&i1)[j] - (((const float*)&f1)[j]*pp + q*((const float*)&g1)[j]);
                float d2 = ((const float*)&i2)[j] - (((const float*)&f2)[j]*pp + q*((const float*)&g2)[j]);
                dc = __fsqrt_rn(fmaf(d0,d0,EPS2)) + __fsqrt_rn(fmaf(d1,d1,EPS2)) + __fsqrt_rn(fmaf(d2,d2,EPS2));
                atomicAdd(&shA[__float_as_uint(da) >> 20], 1u);
                atomicAdd(&shC[__float_as_uint(dc) >> 20], 1u);
                cnt++;
            } else {
                da = __fsqrt_rn(EPS2);              // same formula at d=0 -> monotone ordering holds
                dc = 3.0f * __fsqrt_rn(EPS2);
            }
            ((float*)&va)[j] = da;
            ((float*)&vc)[j] = dc;
        }
        oA[i] = va;
        oC[i] = vc;
    }
    atomicAdd(&shCnt, cnt);
    __syncthreads();
    if (threadIdx.x == 0) atomicAdd(&g_count[b], shCnt);
    for (int i = threadIdx.x; i < NBIN; i += 256) {
        unsigned v = shA[i]; if (v) atomicAdd(&g_hist1[0][b][i], v);
        v = shC[i];          if (v) atomicAdd(&g_hist1[1][b][i], v);
    }
}

// ---------------- K2/K4: warp-per-problem descending histogram scan ----------------
__global__ void k_scan(int pass) {
    const int w    = (int)(threadIdx.x >> 5);
    const int lane = (int)(threadIdx.x & 31);
    if (w >= 2 * BATCH) return;
    const int arr = w / BATCH, b = w % BATCH;

    int k;
    const unsigned* hist;
    if (pass == 1) {
        k = (int)floorf((float)g_count[b] * 0.7f);  // matches jnp.floor(count * 0.7) in f32
        if (arr == 0 && lane == 0) g_k[b] = k;
        hist = g_hist1[arr][b];
    } else {
        k = (int)g_krem1[arr][b];
        hist = g_hist2[arr][b];
    }
    if (k <= 0) {
        if (lane == 0) {
            if (pass == 1) { g_pfx12[arr][b] = 0xFFFFFFFFu; g_krem1[arr][b] = 0u; }
            else           { g_pfx24[arr][b] = 0xFFFFFFFFu; g_krem2[arr][b] = 0u; }
        }
        return;
    }
    int cum = 0;
    for (int c = 0; c < NBIN / 32; c++) {
        const int bin = NBIN - 1 - c * 32 - lane;   // lane 0 = highest bin in chunk
        unsigned h = hist[bin];
        unsigned pfx = h;
        #pragma unroll
        for (int d = 1; d < 32; d <<= 1) {
            unsigned tshf = __shfl_up_sync(0xFFFFFFFFu, pfx, d);
            if (lane >= d) pfx += tshf;
        }
        unsigned bal = __ballot_sync(0xFFFFFFFFu, (cum + (int)pfx) >= k);
        if (bal) {
            int first = __ffs((int)bal) - 1;
            if (lane == first) {
                unsigned krem = (unsigned)(k - cum) - (pfx - h);   // >= 1
                if (pass == 1) { g_pfx12[arr][b] = (unsigned)bin; g_krem1[arr][b] = krem; }
                else           { g_pfx24[arr][b] = (g_pfx12[arr][b] << 12) | (unsigned)bin;
                                 g_krem2[arr][b] = krem; }
            }
            return;
        }
        cum += (int)__shfl_sync(0xFFFFFFFFu, pfx, 31);
    }
}

// ---------------- K3: second-level 12-bit histogram of prefix-matching values ----------------
__global__ __launch_bounds__(256) void k_hist2() {
    __shared__ unsigned sh[NBIN];
    for (int i = threadIdx.x; i < NBIN; i += 256) sh[i] = 0u;
    __syncthreads();

    const int blk = blockIdx.x;                     // 2*BATCH*CH3 blocks
    const int arr = blk / (BATCH * CH3);
    const int b   = (blk / CH3) % BATCH;
    const int c   = blk % CH3;
    const unsigned pfx = g_pfx12[arr][b];
    const float*  srcp = (arr ? g_valC : g_valA) + (size_t)b * NPX + c * (NPX / CH3);
    const float4* src  = (const float4*)srcp;

    const int NIT = (NPX / CH3) / 4;                // 4096 float4 per block
    for (int i = threadIdx.x; i < NIT; i += 256) {
        float4 v = src[i];
        #pragma unroll
        for (int j = 0; j < 4; j++) {
            unsigned u = __float_as_uint(((const float*)&v)[j]);
            if ((u >> 20) == pfx) atomicAdd(&sh[(u >> 8) & 0xFFFu], 1u);
        }
    }
    __syncthreads();
    for (int i = threadIdx.x; i < NBIN; i += 256) {
        unsigned v = sh[i];
        if (v) atomicAdd(&g_hist2[arr][b][i], v);
    }
}

// ---------------- K5: exact sum-above (fixed-point u64) + low-8-bit histogram ----------------
__global__ __launch_bounds__(256) void k_sumpass() {
    __shared__ unsigned shc[256];
    __shared__ unsigned long long shs;
    shc[threadIdx.x] = 0u;
    if (threadIdx.x == 0) shs = 0ull;
    __syncthreads();

    const int blk = blockIdx.x;
    const int arr = blk / (BATCH * CH3);
    const int b   = (blk / CH3) % BATCH;
    const int c   = blk % CH3;
    const unsigned pfx24 = g_pfx24[arr][b];
    const float*  srcp = (arr ? g_valC : g_valA) + (size_t)b * NPX + c * (NPX / CH3);
    const float4* src  = (const float4*)srcp;

    unsigned long long s = 0ull;
    const int NIT = (NPX / CH3) / 4;
    for (int i = threadIdx.x; i < NIT; i += 256) {
        float4 v = src[i];
        #pragma unroll
        for (int j = 0; j < 4; j++) {
            float    vj  = ((const float*)&v)[j];
            unsigned u   = __float_as_uint(vj);
            unsigned top = u >> 8;
            if (top > pfx24) {
                s += (unsigned long long)((double)vj * SCALE_D);
            } else if (top == pfx24) {
                atomicAdd(&shc[u & 0xFFu], 1u);
            }
        }
    }
    if (s) atomicAdd(&shs, s);
    __syncthreads();
    if (threadIdx.x == 0 && shs) atomicAdd(&g_sumAbove[arr][b], shs);
    unsigned v = shc[threadIdx.x];
    if (v) atomicAdd(&g_hist3[arr][b][threadIdx.x], v);
}

// ---------------- K6: finish — tie-exact top-k sums, normalize, average ----------------
__global__ void k_final(float* __restrict__ out) {
    __shared__ double losses[2 * BATCH];
    const int t = threadIdx.x;
    if (t < 2 * BATCH) {
        const int arr = t / BATCH, b = t % BATCH;
        const int k = g_k[b];
        double loss = 0.0;
        if (k > 0) {
            double total = (double)g_sumAbove[arr][b] / SCALE_D;
            unsigned rem   = g_krem2[arr][b];
            unsigned pfx24 = g_pfx24[arr][b];
            for (int bin = 255; bin >= 0 && rem > 0u; bin--) {
                unsigned c = g_hist3[arr][b][bin];
                if (!c) continue;
                float v = __uint_as_float((pfx24 << 8) | (unsigned)bin);
                unsigned take = c < rem ? c : rem;
                total += (double)take * (double)v;
                rem -= take;
            }
            loss = total / ((double)k + 1e-6);
        }
        losses[t] = loss;
    }
    __syncthreads();
    if (t == 0) {
        double sA = 0.0, sC = 0.0;
        for (int b = 0; b < BATCH; b++) { sA += losses[b]; sC += losses[BATCH + b]; }
        float la = (float)(sA / (double)BATCH);
        float lc = (float)(sC / (double)BATCH);
        out[0] = 0.5f * la + 0.5f * lc;
    }
}

// ---------------- launch ----------------
extern "C" void kernel_launch(void* const* d_in, const int* in_sizes, int n_in,
                              void* d_out, int out_size)
{
    const float* image  = (const float*)d_in[0];
    const float* alpha  = (const float*)d_in[1];
    const float* pred   = (const float*)d_in[2];
    const int*   trimap = (const int*)  d_in[3];
    const float* fg     = (const float*)d_in[4];
    const float* bg     = (const float*)d_in[5];

    k_zero<<<(2 * BATCH * NBIN + 255) / 256, 256>>>();
    k_compute<<<BATCH * BPS, 256>>>(image, alpha, pred, trimap, fg, bg);
    k_scan<<<1, 512>>>(1);
    k_hist2<<<2 * BATCH * CH3, 256>>>();
    k_scan<<<1, 512>>>(2);
    k_sumpass<<<2 * BATCH * CH3, 256>>>();
    k_final<<<1, 32>>>((float*)d_out);
}

// round 2
// speedup vs baseline: 4.1697x; 4.1697x over previous
#include <cuda_runtime.h>
#include <cuda_fp16.h>

#define BATCH 8
#define NPX   (512*512)          // 262144 pixels per sample
#define BPS   128                // K1 blocks per sample -> 1024 blocks
#define NBIN1 2048               // top-12-bit half histogram
#define CH3   32                 // K3 chunks per (arr,sample) -> 512 blocks
#define EPS   1e-6f
#define SCALE_D 1099511627776.0  // 2^40 fixed-point scale

// ---------------- device scratch (static; no allocations) ----------------
__device__ __half    g_valA[BATCH*NPX];          // alpha-diff values (fp16)
__device__ __half    g_valC[BATCH*NPX];          // comp-diff values (fp16)
__device__ unsigned  g_count[BATCH];             // # unknown pixels
__device__ int       g_k[BATCH];                 // top-k count per sample
__device__ unsigned  g_hist1[2][BATCH][NBIN1];   // top-12-bit histograms
__device__ unsigned  g_hist16[2][BATCH][16];     // low-4-bit sub-histogram of cut bin
__device__ unsigned  g_pfx[2][BATCH];            // selected 12-bit prefix
__device__ unsigned  g_krem[2][BATCH];           // elements still needed from cut bin
__device__ unsigned long long g_sum[2][BATCH];   // fixed-point sum of values above cut bin

// ---------------- K0: zero accumulators (32768 threads exactly covers hist1) ----
__global__ void k_zero() {
    unsigned idx = blockIdx.x * 256u + threadIdx.x;
    ((unsigned*)g_hist1)[idx] = 0u;
    if (idx < 2u * BATCH * 16u) ((unsigned*)g_hist16)[idx] = 0u;
    if (idx < 2u * BATCH)       ((unsigned long long*)g_sum)[idx] = 0ull;
    if (idx < BATCH)            g_count[idx] = 0u;
}

// ---------------- K1: fused value compute (no MUFU) + count + 12-bit hist ----
__global__ __launch_bounds__(256) void k_compute(
    const float* __restrict__ image, const float* __restrict__ alpha,
    const float* __restrict__ pred,  const int*   __restrict__ trimap,
    const float* __restrict__ fg,    const float* __restrict__ bg)
{
    __shared__ unsigned shA[NBIN1];
    __shared__ unsigned shC[NBIN1];
    __shared__ unsigned shCnt;
    #pragma unroll
    for (int i = threadIdx.x; i < NBIN1; i += 256) { shA[i] = 0u; shC[i] = 0u; }
    if (threadIdx.x == 0) shCnt = 0u;
    __syncthreads();

    const int b     = blockIdx.x >> 7;              // / BPS
    const int chunk = blockIdx.x & (BPS - 1);
    const int base  = chunk * (NPX / BPS);          // 2048-pixel chunk
    const int CH4   = NPX / 4;                      // channel stride in float4

    const float4* al4 = (const float4*)(alpha  + (size_t)b * NPX + base);
    const float4* pr4 = (const float4*)(pred   + (size_t)b * NPX + base);
    const int4*   tm4 = (const int4*)  (trimap + (size_t)b * NPX + base);
    const float4* im4 = (const float4*)(image  + (size_t)b * 3 * NPX + base);
    const float4* fg4 = (const float4*)(fg     + (size_t)b * 3 * NPX + base);
    const float4* bg4 = (const float4*)(bg     + (size_t)b * 3 * NPX + base);
    uint2* oA = (uint2*)(g_valA + (size_t)b * NPX + base);
    uint2* oC = (uint2*)(g_valC + (size_t)b * NPX + base);

    const unsigned short HEPS  = __half_as_ushort(__float2half_rn(EPS));
    const unsigned short HEPS3 = __half_as_ushort(__float2half_rn(3.0f * EPS));

    unsigned cnt = 0;
    #pragma unroll
    for (int it = 0; it < (NPX / BPS) / 4 / 256; it++) {   // 2 iterations
        const int i = it * 256 + threadIdx.x;
        int4   t  = tm4[i];
        float4 a  = al4[i], p = pr4[i];
        float4 i0 = im4[i], i1 = im4[i + CH4], i2 = im4[i + 2*CH4];
        float4 f0 = fg4[i], f1 = fg4[i + CH4], f2 = fg4[i + 2*CH4];
        float4 g0 = bg4[i], g1 = bg4[i + CH4], g2 = bg4[i + 2*CH4];
        unsigned short ha[4], hc[4];
        #pragma unroll
        for (int j = 0; j < 4; j++) {
            const int   tt = ((const int*)&t)[j];
            const float pp = ((const float*)&p)[j];
            if (tt == 128) {
                float d  = fabsf(fmaf(((const float*)&a)[j], 1.0f/255.0f, -pp));
                float da = fmaxf(d, EPS);
                float t0 = fmaf(((const float*)&f0)[j] - ((const float*)&g0)[j], pp, ((const float*)&g0)[j]);
                float t1 = fmaf(((const float*)&f1)[j] - ((const float*)&g1)[j], pp, ((const float*)&g1)[j]);
                float t2 = fmaf(((const float*)&f2)[j] - ((const float*)&g2)[j], pp, ((const float*)&g2)[j]);
                float dc = fmaxf(fabsf(((const float*)&i0)[j] - t0), EPS)
                         + fmaxf(fabsf(((const float*)&i1)[j] - t1), EPS)
                         + fmaxf(fabsf(((const float*)&i2)[j] - t2), EPS);
                ha[j] = __half_as_ushort(__float2half_rn(da));
                hc[j] = __half_as_ushort(__float2half_rn(dc));
                atomicAdd(&shA[ha[j] >> 4], 1u);
                atomicAdd(&shC[hc[j] >> 4], 1u);
                cnt++;
            } else {
                ha[j] = HEPS;
                hc[j] = HEPS3;
            }
        }
        uint2 va, vc;
        va.x = (unsigned)ha[0] | ((unsigned)ha[1] << 16);
        va.y = (unsigned)ha[2] | ((unsigned)ha[3] << 16);
        vc.x = (unsigned)hc[0] | ((unsigned)hc[1] << 16);
        vc.y = (unsigned)hc[2] | ((unsigned)hc[3] << 16);
        oA[i] = va;
        oC[i] = vc;
    }
    cnt = __reduce_add_sync(0xFFFFFFFFu, cnt);
    if ((threadIdx.x & 31) == 0 && cnt) atomicAdd(&shCnt, cnt);
    __syncthreads();
    if (threadIdx.x == 0 && shCnt) atomicAdd(&g_count[b], shCnt);
    #pragma unroll
    for (int i = threadIdx.x; i < NBIN1; i += 256) {
        unsigned v = shA[i]; if (v) atomicAdd(&g_hist1[0][b][i], v);
        v = shC[i];          if (v) atomicAdd(&g_hist1[1][b][i], v);
    }
}

// ---------------- K2: warp-per-problem descending histogram scan ----------------
__global__ void k_scan() {
    const int w    = (int)(threadIdx.x >> 5);
    const int lane = (int)(threadIdx.x & 31);
    if (w >= 2 * BATCH) return;
    const int arr = w / BATCH, b = w % BATCH;

    const int k = (int)floorf((float)g_count[b] * 0.7f);   // matches jnp.floor in f32
    if (arr == 0 && lane == 0) g_k[b] = k;
    if (k <= 0) {
        if (lane == 0) { g_pfx[arr][b] = 0xFFFFFFFFu; g_krem[arr][b] = 0u; }
        return;
    }
    const unsigned* hist = g_hist1[arr][b];
    int cum = 0;
    for (int c = 0; c < NBIN1 / 32; c++) {
        const int bin = NBIN1 - 1 - c * 32 - lane;   // lane 0 = highest bin in chunk
        unsigned h = hist[bin];
        unsigned pfx = h;
        #pragma unroll
        for (int d = 1; d < 32; d <<= 1) {
            unsigned s = __shfl_up_sync(0xFFFFFFFFu, pfx, d);
            if (lane >= d) pfx += s;
        }
        unsigned bal = __ballot_sync(0xFFFFFFFFu, (cum + (int)pfx) >= k);
        if (bal) {
            int first = __ffs((int)bal) - 1;
            if (lane == first) {
                g_pfx[arr][b]  = (unsigned)bin;
                g_krem[arr][b] = (unsigned)(k - cum) - (pfx - h);   // >= 1
            }
            return;
        }
        cum += (int)__shfl_sync(0xFFFFFFFFu, pfx, 31);
    }
}

// ---------------- K3: sum above cut bin (u64 fixed point) + low-4-bit sub-hist ----
__global__ __launch_bounds__(256) void k_sumpass() {
    __shared__ unsigned sh16[16];
    __shared__ unsigned long long shs;
    if (threadIdx.x < 16) sh16[threadIdx.x] = 0u;
    if (threadIdx.x == 0) shs = 0ull;
    __syncthreads();

    const int blk = blockIdx.x;                      // 2*BATCH*CH3 blocks
    const int arr = blk / (BATCH * CH3);
    const int b   = (blk / CH3) % BATCH;
    const int c   = blk % CH3;
    const unsigned pfx = g_pfx[arr][b];
    const __half* srcp = (arr ? g_valC : g_valA) + (size_t)b * NPX + c * (NPX / CH3);
    const uint4*  src  = (const uint4*)srcp;         // 8 halves per load

    float fsum = 0.0f;
    #pragma unroll
    for (int it = 0; it < (NPX / CH3) / 8 / 256; it++) {   // 4 iterations
        uint4 v = src[it * 256 + threadIdx.x];
        const unsigned wv[4] = {v.x, v.y, v.z, v.w};
        #pragma unroll
        for (int q = 0; q < 4; q++) {
            #pragma unroll
            for (int h = 0; h < 2; h++) {
                unsigned hb  = (wv[q] >> (16 * h)) & 0xFFFFu;
                unsigned bin = hb >> 4;
                if (bin > pfx) {
                    fsum += __half2float(__ushort_as_half((unsigned short)hb));
                } else if (bin == pfx) {
                    atomicAdd(&sh16[hb & 15u], 1u);
                }
            }
        }
    }
    // deterministic warp tree-reduce, then fixed-point conversion
    #pragma unroll
    for (int o = 16; o; o >>= 1) fsum += __shfl_xor_sync(0xFFFFFFFFu, fsum, o);
    if ((threadIdx.x & 31) == 0 && fsum != 0.0f)
        atomicAdd(&shs, (unsigned long long)((double)fsum * SCALE_D));
    __syncthreads();
    if (threadIdx.x == 0 && shs) atomicAdd(&g_sum[arr][b], shs);
    if (threadIdx.x < 16) {
        unsigned v = sh16[threadIdx.x];
        if (v) atomicAdd(&g_hist16[arr][b][threadIdx.x], v);
    }
}

// ---------------- K4: finish — tie-exact at fp16 granularity, normalize, average ----
__global__ void k_final(float* __restrict__ out) {
    __shared__ double losses[2 * BATCH];
    const int t = threadIdx.x;
    if (t < 2 * BATCH) {
        const int arr = t / BATCH, b = t % BATCH;
        const int k = g_k[b];
        double loss = 0.0;
        if (k > 0) {
            double total = (double)g_sum[arr][b] / SCALE_D;
            unsigned rem = g_krem[arr][b];
            const unsigned pfx = g_pfx[arr][b];
            for (int sub = 15; sub >= 0 && rem > 0u; sub--) {
                unsigned c = g_hist16[arr][b][sub];
                if (!c) continue;
                unsigned take = c < rem ? c : rem;
                float v = __half2float(__ushort_as_half((unsigned short)((pfx << 4) | (unsigned)sub)));
                total += (double)take * (double)v;
                rem -= take;
            }
            loss = total / ((double)k + 1e-6);
        }
        losses[t] = loss;
    }
    __syncthreads();
    if (t == 0) {
        double sA = 0.0, sC = 0.0;
        for (int b = 0; b < BATCH; b++) { sA += losses[b]; sC += losses[BATCH + b]; }
        out[0] = 0.5f * (float)(sA / (double)BATCH) + 0.5f * (float)(sC / (double)BATCH);
    }
}

// ---------------- launch ----------------
extern "C" void kernel_launch(void* const* d_in, const int* in_sizes, int n_in,
                              void* d_out, int out_size)
{
    const float* image  = (const float*)d_in[0];
    const float* alpha  = (const float*)d_in[1];
    const float* pred   = (const float*)d_in[2];
    const int*   trimap = (const int*)  d_in[3];
    const float* fg     = (const float*)d_in[4];
    const float* bg     = (const float*)d_in[5];

    k_zero<<<(2 * BATCH * NBIN1) / 256, 256>>>();
    k_compute<<<BATCH * BPS, 256>>>(image, alpha, pred, trimap, fg, bg);
    k_scan<<<1, 512>>>();
    k_sumpass<<<2 * BATCH * CH3, 256>>>();
    k_final<<<1, 32>>>((float*)d_out);
}

// round 3
// speedup vs baseline: 7.1333x; 1.7108x over previous
#include <cuda_runtime.h>
#include <cuda_fp16.h>

#define BATCH 8
#define NPX   (512*512)          // 262144 pixels per sample
#define BPS   128                // K1 blocks per sample -> 1024 blocks
#define NBIN1 2048               // top-12-bit half histogram
#define CH3   64                 // K3 chunks per (arr,sample) -> 1024 blocks
#define EPS   1e-6f
#define SCALE_D 1099511627776.0  // 2^40 fixed-point scale

// ---------------- device scratch (static; zero-init at load, re-zeroed by k_final) ----
__device__ __half    g_valA[BATCH*NPX];          // alpha-diff values (fp16)
__device__ __half    g_valC[BATCH*NPX];          // comp-diff values (fp16)
__device__ unsigned  g_count[BATCH];             // # unknown pixels
__device__ unsigned  g_hist1[2][BATCH][NBIN1];   // top-12-bit histograms
__device__ unsigned  g_hist16[2][BATCH][16];     // low-4-bit sub-histogram of cut bin
__device__ unsigned  g_pfx[2][BATCH];            // selected 12-bit prefix (for k_final)
__device__ unsigned  g_krem[2][BATCH];           // elements still needed from cut bin
__device__ unsigned long long g_sum[2][BATCH];   // fixed-point sum of values above cut bin

// ---------------- K1: fused value compute (no MUFU) + count + 12-bit hist ----
__global__ __launch_bounds__(256) void k_compute(
    const float* __restrict__ image, const float* __restrict__ alpha,
    const float* __restrict__ pred,  const int*   __restrict__ trimap,
    const float* __restrict__ fg,    const float* __restrict__ bg)
{
    __shared__ unsigned shA[NBIN1];
    __shared__ unsigned shC[NBIN1];
    __shared__ unsigned shCnt;
    #pragma unroll
    for (int i = threadIdx.x; i < NBIN1; i += 256) { shA[i] = 0u; shC[i] = 0u; }
    if (threadIdx.x == 0) shCnt = 0u;
    __syncthreads();

    const int b     = blockIdx.x >> 7;              // / BPS
    const int chunk = blockIdx.x & (BPS - 1);
    const int base  = chunk * (NPX / BPS);          // 2048-pixel chunk
    const int CH4   = NPX / 4;                      // channel stride in float4

    const float4* al4 = (const float4*)(alpha  + (size_t)b * NPX + base);
    const float4* pr4 = (const float4*)(pred   + (size_t)b * NPX + base);
    const int4*   tm4 = (const int4*)  (trimap + (size_t)b * NPX + base);
    const float4* im4 = (const float4*)(image  + (size_t)b * 3 * NPX + base);
    const float4* fg4 = (const float4*)(fg     + (size_t)b * 3 * NPX + base);
    const float4* bg4 = (const float4*)(bg     + (size_t)b * 3 * NPX + base);
    uint2* oA = (uint2*)(g_valA + (size_t)b * NPX + base);
    uint2* oC = (uint2*)(g_valC + (size_t)b * NPX + base);

    const unsigned short HEPS  = __half_as_ushort(__float2half_rn(EPS));
    const unsigned short HEPS3 = __half_as_ushort(__float2half_rn(3.0f * EPS));

    unsigned cnt = 0;
    #pragma unroll
    for (int it = 0; it < (NPX / BPS) / 4 / 256; it++) {   // 2 iterations
        const int i = it * 256 + threadIdx.x;
        int4   t  = tm4[i];
        float4 a  = al4[i], p = pr4[i];
        float4 i0 = im4[i], i1 = im4[i + CH4], i2 = im4[i + 2*CH4];
        float4 f0 = fg4[i], f1 = fg4[i + CH4], f2 = fg4[i + 2*CH4];
        float4 g0 = bg4[i], g1 = bg4[i + CH4], g2 = bg4[i + 2*CH4];
        unsigned short ha[4], hc[4];
        #pragma unroll
        for (int j = 0; j < 4; j++) {
            const int   tt = ((const int*)&t)[j];
            const float pp = ((const float*)&p)[j];
            if (tt == 128) {
                float d  = fabsf(fmaf(((const float*)&a)[j], 1.0f/255.0f, -pp));
                float da = fmaxf(d, EPS);
                float t0 = fmaf(((const float*)&f0)[j] - ((const float*)&g0)[j], pp, ((const float*)&g0)[j]);
                float t1 = fmaf(((const float*)&f1)[j] - ((const float*)&g1)[j], pp, ((const float*)&g1)[j]);
                float t2 = fmaf(((const float*)&f2)[j] - ((const float*)&g2)[j], pp, ((const float*)&g2)[j]);
                float dc = fmaxf(fabsf(((const float*)&i0)[j] - t0), EPS)
                         + fmaxf(fabsf(((const float*)&i1)[j] - t1), EPS)
                         + fmaxf(fabsf(((const float*)&i2)[j] - t2), EPS);
                ha[j] = __half_as_ushort(__float2half_rn(da));
                hc[j] = __half_as_ushort(__float2half_rn(dc));
                atomicAdd(&shA[ha[j] >> 4], 1u);
                atomicAdd(&shC[hc[j] >> 4], 1u);
                cnt++;
            } else {
                ha[j] = HEPS;
                hc[j] = HEPS3;
            }
        }
        uint2 va, vc;
        va.x = (unsigned)ha[0] | ((unsigned)ha[1] << 16);
        va.y = (unsigned)ha[2] | ((unsigned)ha[3] << 16);
        vc.x = (unsigned)hc[0] | ((unsigned)hc[1] << 16);
        vc.y = (unsigned)hc[2] | ((unsigned)hc[3] << 16);
        oA[i] = va;
        oC[i] = vc;
    }
    cnt = __reduce_add_sync(0xFFFFFFFFu, cnt);
    if ((threadIdx.x & 31) == 0 && cnt) atomicAdd(&shCnt, cnt);
    __syncthreads();
    if (threadIdx.x == 0 && shCnt) atomicAdd(&g_count[b], shCnt);
    #pragma unroll
    for (int i = threadIdx.x; i < NBIN1; i += 256) {
        unsigned v = shA[i]; if (v) atomicAdd(&g_hist1[0][b][i], v);
        v = shC[i];          if (v) atomicAdd(&g_hist1[1][b][i], v);
    }
}

// ---------------- K2: inline cut-scan + sum above cut bin + low-4-bit sub-hist ----
__global__ __launch_bounds__(256) void k_sumpass() {
    __shared__ unsigned s_seg[256];
    __shared__ unsigned s_pfx, s_krem;
    __shared__ unsigned sh16[16];
    __shared__ unsigned long long shs;

    const int blk = blockIdx.x;                      // 2*BATCH*CH3 blocks
    const int arr = blk / (BATCH * CH3);
    const int b   = (blk / CH3) % BATCH;
    const int c   = blk % CH3;
    const int t   = threadIdx.x;

    if (t < 16) sh16[t] = 0u;
    if (t == 0) { shs = 0ull; s_pfx = 0xFFFFFFFFu; s_krem = 0u; }

    // ---- inline descending scan of g_hist1[arr][b] to find cut bin ----
    const unsigned* hist = g_hist1[arr][b];
    // thread t owns bins [2040-8t .. 2047-8t]; t ascending = value descending
    uint4 h0 = *(const uint4*)&hist[2040 - 8 * t];   // bins 2040..2043 - 8t
    uint4 h1 = *(const uint4*)&hist[2044 - 8 * t];   // bins 2044..2047 - 8t
    unsigned seg = h0.x + h0.y + h0.z + h0.w + h1.x + h1.y + h1.z + h1.w;
    s_seg[t] = seg;
    __syncthreads();
    #pragma unroll
    for (int d = 1; d < 256; d <<= 1) {               // Hillis-Steele inclusive scan
        unsigned v = (t >= d) ? s_seg[t - d] : 0u;
        __syncthreads();
        s_seg[t] += v;
        __syncthreads();
    }
    const unsigned k = (unsigned)(int)floorf((float)g_count[b] * 0.7f);
    {
        unsigned incl = s_seg[t];
        unsigned excl = incl - seg;
        if (k > 0u && excl < k && incl >= k) {        // exactly one owner thread
            unsigned bins[8] = {h1.w, h1.z, h1.y, h1.x, h0.w, h0.z, h0.y, h0.x};
            unsigned cum = excl;
            #pragma unroll
            for (int j = 0; j < 8; j++) {
                cum += bins[j];
                if (cum >= k) {
                    s_pfx  = (unsigned)(2047 - 8 * t - j);
                    s_krem = k - (cum - bins[j]);     // >= 1
                    break;
                }
            }
        }
    }
    __syncthreads();
    const unsigned pfx = s_pfx;
    if (c == 0 && t == 0) { g_pfx[arr][b] = pfx; g_krem[arr][b] = s_krem; }

    // ---- main sum pass over this block's scratch chunk ----
    const __half* srcp = (arr ? g_valC : g_valA) + (size_t)b * NPX + c * (NPX / CH3);
    const uint4*  src  = (const uint4*)srcp;         // 8 halves per load

    float fsum = 0.0f;
    #pragma unroll
    for (int it = 0; it < (NPX / CH3) / 8 / 256; it++) {   // 2 iterations
        uint4 v = src[it * 256 + t];
        const unsigned wv[4] = {v.x, v.y, v.z, v.w};
        #pragma unroll
        for (int q = 0; q < 4; q++) {
            #pragma unroll
            for (int h = 0; h < 2; h++) {
                unsigned hb  = (wv[q] >> (16 * h)) & 0xFFFFu;
                unsigned bin = hb >> 4;
                if (bin > pfx) {
                    fsum += __half2float(__ushort_as_half((unsigned short)hb));
                } else if (bin == pfx) {
                    atomicAdd(&sh16[hb & 15u], 1u);
                }
            }
        }
    }
    // deterministic warp tree-reduce, then fixed-point conversion
    #pragma unroll
    for (int o = 16; o; o >>= 1) fsum += __shfl_xor_sync(0xFFFFFFFFu, fsum, o);
    if ((t & 31) == 0 && fsum != 0.0f)
        atomicAdd(&shs, (unsigned long long)((double)fsum * SCALE_D));
    __syncthreads();
    if (t == 0 && shs) atomicAdd(&g_sum[arr][b], shs);
    if (t < 16) {
        unsigned v = sh16[t];
        if (v) atomicAdd(&g_hist16[arr][b][t], v);
    }
}

// ---------------- K3: finish (block 0) + re-zero accumulators (all blocks) ----
__global__ __launch_bounds__(256) void k_final(float* __restrict__ out) {
    const int t = threadIdx.x;
    if (blockIdx.x != 0) {
        // zero g_hist1: 32768 words over 64 blocks, 2 words per thread
        unsigned base = (blockIdx.x - 1) * 512u + (unsigned)t;
        ((unsigned*)g_hist1)[base]        = 0u;
        ((unsigned*)g_hist1)[base + 256u] = 0u;
        return;
    }
    __shared__ double losses[2 * BATCH];
    if (t < 2 * BATCH) {
        const int arr = t / BATCH, b = t % BATCH;
        const int k = (int)floorf((float)g_count[b] * 0.7f);
        double loss = 0.0;
        if (k > 0) {
            double total = (double)g_sum[arr][b] / SCALE_D;
            unsigned rem = g_krem[arr][b];
            const unsigned pfx = g_pfx[arr][b];
            for (int sub = 15; sub >= 0 && rem > 0u; sub--) {
                unsigned cc = g_hist16[arr][b][sub];
                if (!cc) continue;
                unsigned take = cc < rem ? cc : rem;
                float v = __half2float(__ushort_as_half((unsigned short)((pfx << 4) | (unsigned)sub)));
                total += (double)take * (double)v;
                rem -= take;
            }
            loss = total / ((double)k + 1e-6);
        }
        losses[t] = loss;
    }
    __syncthreads();                                  // all reads of accumulators done
    if (t == 0) {
        double sA = 0.0, sC = 0.0;
        for (int b = 0; b < BATCH; b++) { sA += losses[b]; sC += losses[BATCH + b]; }
        out[0] = 0.5f * (float)(sA / (double)BATCH) + 0.5f * (float)(sC / (double)BATCH);
    }
    // re-zero small accumulators for the next graph replay
    ((unsigned*)g_hist16)[t] = 0u;                    // 256 words
    if (t < 2 * BATCH) ((unsigned long long*)g_sum)[t] = 0ull;
    if (t < BATCH)     g_count[t] = 0u;
}

// ---------------- launch ----------------
extern "C" void kernel_launch(void* const* d_in, const int* in_sizes, int n_in,
                              void* d_out, int out_size)
{
    const float* image  = (const float*)d_in[0];
    const float* alpha  = (const float*)d_in[1];
    const float* pred   = (const float*)d_in[2];
    const int*   trimap = (const int*)  d_in[3];
    const float* fg     = (const float*)d_in[4];
    const float* bg     = (const float*)d_in[5];

    k_compute<<<BATCH * BPS, 256>>>(image, alpha, pred, trimap, fg, bg);
    k_sumpass<<<2 * BATCH * CH3, 256>>>();
    k_final<<<65, 256>>>((float*)d_out);
}

// round 4
// speedup vs baseline: 7.2373x; 1.0146x over previous
#include <cuda_runtime.h>
#include <cuda_fp16.h>

#define BATCH 8
#define NPX   (512*512)          // 262144 pixels per sample
#define BPS   64                 // K1 blocks per sample -> 512 blocks (1 full wave @5/SM)
#define NBIN1 2048               // top-12-bit half histogram
#define CH3   64                 // K2 chunks per (arr,sample) -> 1024 blocks
#define EPS   1e-6f
#define SCALE_D 1099511627776.0  // 2^40 fixed-point scale

// ---------------- device scratch (static; zero-init at load, re-zeroed by k_final) ----
__device__ __half    g_valA[BATCH*NPX];          // alpha-diff values (fp16)
__device__ __half    g_valC[BATCH*NPX];          // comp-diff values (fp16)
__device__ unsigned  g_count[BATCH];             // # unknown pixels
__device__ unsigned  g_hist1[2][BATCH][NBIN1];   // top-12-bit histograms
__device__ unsigned  g_hist16[2][BATCH][16];     // low-4-bit sub-histogram of cut bin
__device__ unsigned  g_pfx[2][BATCH];            // selected 12-bit prefix (for k_final)
__device__ unsigned  g_krem[2][BATCH];           // elements still needed from cut bin
__device__ unsigned long long g_sum[2][BATCH];   // fixed-point sum of values above cut bin

// ---------------- K1: fused value compute + count + 12-bit hist (reg-lean) ----
__global__ __launch_bounds__(256, 5) void k_compute(
    const float* __restrict__ image, const float* __restrict__ alpha,
    const float* __restrict__ pred,  const int*   __restrict__ trimap,
    const float* __restrict__ fg,    const float* __restrict__ bg)
{
    __shared__ unsigned shA[NBIN1];
    __shared__ unsigned shC[NBIN1];
    __shared__ unsigned shCnt;
    #pragma unroll
    for (int i = threadIdx.x; i < NBIN1; i += 256) { shA[i] = 0u; shC[i] = 0u; }
    if (threadIdx.x == 0) shCnt = 0u;
    __syncthreads();

    const int b     = blockIdx.x >> 6;              // / BPS
    const int chunk = blockIdx.x & (BPS - 1);
    const int base  = chunk * (NPX / BPS);          // 4096-pixel chunk
    const int CH4   = NPX / 4;                      // channel stride in float4

    const float4* al4 = (const float4*)(alpha  + (size_t)b * NPX + base);
    const float4* pr4 = (const float4*)(pred   + (size_t)b * NPX + base);
    const int4*   tm4 = (const int4*)  (trimap + (size_t)b * NPX + base);
    const float4* im4 = (const float4*)(image  + (size_t)b * 3 * NPX + base);
    const float4* fg4 = (const float4*)(fg     + (size_t)b * 3 * NPX + base);
    const float4* bg4 = (const float4*)(bg     + (size_t)b * 3 * NPX + base);
    uint2* oA = (uint2*)(g_valA + (size_t)b * NPX + base);
    uint2* oC = (uint2*)(g_valC + (size_t)b * NPX + base);

    const unsigned short HEPS  = __half_as_ushort(__float2half_rn(EPS));
    const unsigned short HEPS3 = __half_as_ushort(__float2half_rn(3.0f * EPS));

    unsigned cnt = 0;
    for (int it = 0; it < (NPX / BPS) / 4 / 256; it++) {   // 4 iterations
        const int i = it * 256 + threadIdx.x;
        const int4   t = __ldcs(tm4 + i);
        const float4 a = __ldcs(al4 + i);
        const float4 p = __ldcs(pr4 + i);

        float da[4], dc[4];
        #pragma unroll
        for (int j = 0; j < 4; j++) {
            da[j] = fmaxf(fabsf(fmaf(((const float*)&a)[j], 1.0f/255.0f,
                                     -((const float*)&p)[j])), EPS);
            dc[j] = 0.0f;
        }
        #pragma unroll
        for (int ch = 0; ch < 3; ch++) {            // channel-incremental: low live-reg count
            const float4 im = __ldcs(im4 + i + ch * CH4);
            const float4 ff = __ldcs(fg4 + i + ch * CH4);
            const float4 gg = __ldcs(bg4 + i + ch * CH4);
            #pragma unroll
            for (int j = 0; j < 4; j++) {
                float pj = ((const float*)&p)[j];
                float tt = fmaf(((const float*)&ff)[j] - ((const float*)&gg)[j], pj,
                                ((const float*)&gg)[j]);
                dc[j] += fmaxf(fabsf(((const float*)&im)[j] - tt), EPS);
            }
        }
        unsigned short ha[4], hc[4];
        #pragma unroll
        for (int j = 0; j < 4; j++) {
            const bool u = (((const int*)&t)[j] == 128);
            unsigned short hda = __half_as_ushort(__float2half_rn(da[j]));
            unsigned short hdc = __half_as_ushort(__float2half_rn(dc[j]));
            ha[j] = u ? hda : HEPS;
            hc[j] = u ? hdc : HEPS3;
            if (u) {
                atomicAdd(&shA[hda >> 4], 1u);
                atomicAdd(&shC[hdc >> 4], 1u);
                cnt++;
            }
        }
        uint2 va, vc;
        va.x = (unsigned)ha[0] | ((unsigned)ha[1] << 16);
        va.y = (unsigned)ha[2] | ((unsigned)ha[3] << 16);
        vc.x = (unsigned)hc[0] | ((unsigned)hc[1] << 16);
        vc.y = (unsigned)hc[2] | ((unsigned)hc[3] << 16);
        oA[i] = va;
        oC[i] = vc;
    }
    cnt = __reduce_add_sync(0xFFFFFFFFu, cnt);
    if ((threadIdx.x & 31) == 0 && cnt) atomicAdd(&shCnt, cnt);
    __syncthreads();
    if (threadIdx.x == 0 && shCnt) atomicAdd(&g_count[b], shCnt);
    #pragma unroll
    for (int i = threadIdx.x; i < NBIN1; i += 256) {
        unsigned v = shA[i]; if (v) atomicAdd(&g_hist1[0][b][i], v);
        v = shC[i];          if (v) atomicAdd(&g_hist1[1][b][i], v);
    }
}

// ---------------- K2: inline cut-scan + sum above cut bin + low-4-bit sub-hist ----
__global__ __launch_bounds__(256) void k_sumpass() {
    __shared__ unsigned s_seg[256];
    __shared__ unsigned s_pfx, s_krem;
    __shared__ unsigned sh16[16];
    __shared__ unsigned long long shs;

    const int blk = blockIdx.x;                      // 2*BATCH*CH3 blocks
    const int arr = blk / (BATCH * CH3);
    const int b   = (blk / CH3) % BATCH;
    const int c   = blk % CH3;
    const int t   = threadIdx.x;

    if (t < 16) sh16[t] = 0u;
    if (t == 0) { shs = 0ull; s_pfx = 0xFFFFFFFFu; s_krem = 0u; }

    // ---- inline descending scan of g_hist1[arr][b] to find cut bin ----
    const unsigned* hist = g_hist1[arr][b];
    // thread t owns bins [2040-8t .. 2047-8t]; t ascending = value descending
    uint4 h0 = *(const uint4*)&hist[2040 - 8 * t];
    uint4 h1 = *(const uint4*)&hist[2044 - 8 * t];
    unsigned seg = h0.x + h0.y + h0.z + h0.w + h1.x + h1.y + h1.z + h1.w;
    s_seg[t] = seg;
    __syncthreads();
    #pragma unroll
    for (int d = 1; d < 256; d <<= 1) {               // Hillis-Steele inclusive scan
        unsigned v = (t >= d) ? s_seg[t - d] : 0u;
        __syncthreads();
        s_seg[t] += v;
        __syncthreads();
    }
    const unsigned k = (unsigned)(int)floorf((float)g_count[b] * 0.7f);
    {
        unsigned incl = s_seg[t];
        unsigned excl = incl - seg;
        if (k > 0u && excl < k && incl >= k) {        // exactly one owner thread
            unsigned bins[8] = {h1.w, h1.z, h1.y, h1.x, h0.w, h0.z, h0.y, h0.x};
            unsigned cum = excl;
            #pragma unroll
            for (int j = 0; j < 8; j++) {
                cum += bins[j];
                if (cum >= k) {
                    s_pfx  = (unsigned)(2047 - 8 * t - j);
                    s_krem = k - (cum - bins[j]);     // >= 1
                    break;
                }
            }
        }
    }
    __syncthreads();
    const unsigned pfx = s_pfx;
    if (c == 0 && t == 0) { g_pfx[arr][b] = pfx; g_krem[arr][b] = s_krem; }

    // ---- main sum pass over this block's scratch chunk (L2-resident) ----
    const __half* srcp = (arr ? g_valC : g_valA) + (size_t)b * NPX + c * (NPX / CH3);
    const uint4*  src  = (const uint4*)srcp;         // 8 halves per load

    float fsum = 0.0f;
    #pragma unroll
    for (int it = 0; it < (NPX / CH3) / 8 / 256; it++) {   // 2 iterations
        uint4 v = src[it * 256 + t];
        const unsigned wv[4] = {v.x, v.y, v.z, v.w};
        #pragma unroll
        for (int q = 0; q < 4; q++) {
            #pragma unroll
            for (int h = 0; h < 2; h++) {
                unsigned hb  = (wv[q] >> (16 * h)) & 0xFFFFu;
                unsigned bin = hb >> 4;
                if (bin > pfx) {
                    fsum += __half2float(__ushort_as_half((unsigned short)hb));
                } else if (bin == pfx) {
                    atomicAdd(&sh16[hb & 15u], 1u);
                }
            }
        }
    }
    // deterministic warp tree-reduce, then fixed-point conversion
    #pragma unroll
    for (int o = 16; o; o >>= 1) fsum += __shfl_xor_sync(0xFFFFFFFFu, fsum, o);
    if ((t & 31) == 0 && fsum != 0.0f)
        atomicAdd(&shs, (unsigned long long)((double)fsum * SCALE_D));
    __syncthreads();
    if (t == 0 && shs) atomicAdd(&g_sum[arr][b], shs);
    if (t < 16) {
        unsigned v = sh16[t];
        if (v) atomicAdd(&g_hist16[arr][b][t], v);
    }
}

// ---------------- K3: finish (block 0) + re-zero accumulators (all blocks) ----
__global__ __launch_bounds__(256) void k_final(float* __restrict__ out) {
    const int t = threadIdx.x;
    if (blockIdx.x != 0) {
        // zero g_hist1: 32768 words over 64 blocks, 2 words per thread
        unsigned base = (blockIdx.x - 1) * 512u + (unsigned)t;
        ((unsigned*)g_hist1)[base]        = 0u;
        ((unsigned*)g_hist1)[base + 256u] = 0u;
        return;
    }
    __shared__ double losses[2 * BATCH];
    if (t < 2 * BATCH) {
        const int arr = t / BATCH, b = t % BATCH;
        const int k = (int)floorf((float)g_count[b] * 0.7f);
        double loss = 0.0;
        if (k > 0) {
            double total = (double)g_sum[arr][b] / SCALE_D;
            unsigned rem = g_krem[arr][b];
            const unsigned pfx = g_pfx[arr][b];
            for (int sub = 15; sub >= 0 && rem > 0u; sub--) {
                unsigned cc = g_hist16[arr][b][sub];
                if (!cc) continue;
                unsigned take = cc < rem ? cc : rem;
                float v = __half2float(__ushort_as_half((unsigned short)((pfx << 4) | (unsigned)sub)));
                total += (double)take * (double)v;
                rem -= take;
            }
            loss = total / ((double)k + 1e-6);
        }
        losses[t] = loss;
    }
    __syncthreads();                                  // all reads of accumulators done
    if (t == 0) {
        double sA = 0.0, sC = 0.0;
        for (int b = 0; b < BATCH; b++) { sA += losses[b]; sC += losses[BATCH + b]; }
        out[0] = 0.5f * (float)(sA / (double)BATCH) + 0.5f * (float)(sC / (double)BATCH);
    }
    // re-zero small accumulators for the next graph replay
    ((unsigned*)g_hist16)[t] = 0u;                    // 256 words
    if (t < 2 * BATCH) ((unsigned long long*)g_sum)[t] = 0ull;
    if (t < BATCH)     g_count[t] = 0u;
}

// ---------------- launch ----------------
extern "C" void kernel_launch(void* const* d_in, const int* in_sizes, int n_in,
                              void* d_out, int out_size)
{
    const float* image  = (const float*)d_in[0];
    const float* alpha  = (const float*)d_in[1];
    const float* pred   = (const float*)d_in[2];
    const int*   trimap = (const int*)  d_in[3];
    const float* fg     = (const float*)d_in[4];
    const float* bg     = (const float*)d_in[5];

    k_compute<<<BATCH * BPS, 256>>>(image, alpha, pred, trimap, fg, bg);
    k_sumpass<<<2 * BATCH * CH3, 256>>>();
    k_final<<<65, 256>>>((float*)d_out);
}